// round 14
// baseline (speedup 1.0000x reference)
#include <cuda_runtime.h>

// SoftDTW-variant, gamma=1, B=32, T=512, row-broadcast cost ds[i]=(x[i]-y[i])^2.
// Linear-weight domain: W(i,j) = 2^(P(i) - R(i,j)*log2e), P(i)=sum_{r<=i} ds'[r].
//   W(i,j) = W(i-1,j) + W(i-1,j-1) + c_i * W(i,j-1),  c_i = 2^(-ds'[i]) <= 1
// Guard-free commits, raw u (<= 2^15 by tile path-count bound), joint pre-tile
// renorm to <= 2. 2 warps/batch, 8 cols/lane, 8 rows/superstep, 127 wall slots.
//
// R14: cut per-slot fixed overhead F:
//  - sentinel-in-data seam (write-once ring, 32-bit words never torn): consumer
//    does 10 parallel volatile LDS + IMNMX validity tree; no acquire/release.
//  - producer ships max(nb0..7) through the handoff (shfl + ring word), so the
//    consumer's renorm needs no max-tree on the critical path.
//  - eu computed at tile end (off the inter-slot path).

#define TLEN  512
#define BATCH 32
#define NTH   64
#define ROWS  8
#define RB    (TLEN / ROWS)       // 64 row-blocks
#define WSUP  (RB + 31)           // 95 supersteps per warp
#define SENT  0x7fffffff

__global__ __launch_bounds__(NTH, 1) void softdtw_kernel(const float* __restrict__ x,
                                                         const float* __restrict__ y,
                                                         float* __restrict__ out) {
    __shared__ float cs[TLEN];                       // c_i = 2^{-ds'[i]}
    __shared__ float redsum[2];
    __shared__ __align__(16) int ring[WSUP * 12];    // slot: [0..7] nb, [8] k, [9] mnb, pad

    const int q    = threadIdx.x;
    const int lane = q & 31;
    const int w    = q >> 5;
    const int b    = blockIdx.x;

    // ---- prologue: 8 costs per thread ---------------------------------------
    const float L2E = 1.4426950408889634f;
    float4 xa = ((const float4*)(x + b * TLEN))[2 * q];
    float4 xb = ((const float4*)(x + b * TLEN))[2 * q + 1];
    float4 ya = ((const float4*)(y + b * TLEN))[2 * q];
    float4 yb = ((const float4*)(y + b * TLEN))[2 * q + 1];
    float e0 = (xa.x - ya.x) * (xa.x - ya.x) * L2E;
    float e1 = (xa.y - ya.y) * (xa.y - ya.y) * L2E;
    float e2 = (xa.z - ya.z) * (xa.z - ya.z) * L2E;
    float e3 = (xa.w - ya.w) * (xa.w - ya.w) * L2E;
    float e4 = (xb.x - yb.x) * (xb.x - yb.x) * L2E;
    float e5 = (xb.y - yb.y) * (xb.y - yb.y) * L2E;
    float e6 = (xb.z - yb.z) * (xb.z - yb.z) * L2E;
    float e7 = (xb.w - yb.w) * (xb.w - yb.w) * L2E;
    cs[8*q + 0] = exp2f(-e0);  cs[8*q + 1] = exp2f(-e1);
    cs[8*q + 2] = exp2f(-e2);  cs[8*q + 3] = exp2f(-e3);
    cs[8*q + 4] = exp2f(-e4);  cs[8*q + 5] = exp2f(-e5);
    cs[8*q + 6] = exp2f(-e6);  cs[8*q + 7] = exp2f(-e7);
    float mysum = ((e0 + e1) + (e2 + e3)) + ((e4 + e5) + (e6 + e7));
    #pragma unroll
    for (int o = 16; o; o >>= 1) mysum += __shfl_xor_sync(0xffffffffu, mysum, o);
    if (lane == 0) redsum[w] = mysum;
    for (int i = q; i < WSUP * 12; i += NTH) ring[i] = SENT;
    __syncthreads();
    const float P = redsum[0] + redsum[1];

    unsigned paddr = (unsigned)__cvta_generic_to_shared(ring);  // producer slot ts
    const int pub = (w == 0) && (lane == 31);
    volatile const int* cons = ring + 31 * 12;       // consumer: slot ts+31

    // ---- state --------------------------------------------------------------
    float u0=0.f,u1=0.f,u2=0.f,u3=0.f,u4=0.f,u5=0.f,u6=0.f,u7=0.f; // RAW, frame k
    float nb0=0.f,nb1=0.f,nb2=0.f,nb3=0.f,nb4=0.f,nb5=0.f,nb6=0.f,nb7=0.f; // frame k
    float mnb = 0.0f;                                // max(nb0..7), frame k
    float dgW = (q == 0) ? 1.0f : 0.0f;              // diag input (<= 2), frame k
    int   k = 0, eu = -127;                          // eu = exponent of max(u)

    for (int ts = 0; ts < WSUP; ++ts) {
        // ---- receive left boundary (8 rows) + producer frame + its max ----
        float l0 = __shfl_up_sync(0xffffffffu, nb0, 1);
        float l1 = __shfl_up_sync(0xffffffffu, nb1, 1);
        float l2 = __shfl_up_sync(0xffffffffu, nb2, 1);
        float l3 = __shfl_up_sync(0xffffffffu, nb3, 1);
        float l4 = __shfl_up_sync(0xffffffffu, nb4, 1);
        float l5 = __shfl_up_sync(0xffffffffu, nb5, 1);
        float l6 = __shfl_up_sync(0xffffffffu, nb6, 1);
        float l7 = __shfl_up_sync(0xffffffffu, nb7, 1);
        float mlx = __shfl_up_sync(0xffffffffu, mnb, 1);
        int   kp  = __shfl_up_sync(0xffffffffu, k,   1);

        // ---- seam: sentinel-validated parallel loads (write-once ring) ----
        if ((w == 1) & (ts < RB)) {                  // warp-uniform
            int a0, a1, a2, a3, a4, a5, a6, a7, a8, a9;
            int mxv;
            do {
                a0 = cons[0]; a1 = cons[1]; a2 = cons[2]; a3 = cons[3];
                a4 = cons[4]; a5 = cons[5]; a6 = cons[6]; a7 = cons[7];
                a8 = cons[8]; a9 = cons[9];
                int m01 = a0 > a1 ? a0 : a1;  int m23 = a2 > a3 ? a2 : a3;
                int m45 = a4 > a5 ? a4 : a5;  int m67 = a6 > a7 ? a6 : a7;
                int m89 = a8 > a9 ? a8 : a9;
                int ma = m01 > m23 ? m01 : m23;
                int mb = m45 > m67 ? m45 : m67;
                int mc = ma > mb ? ma : mb;
                mxv = mc > m89 ? mc : m89;
            } while (mxv == SENT);
            if (lane == 0) {
                l0 = __int_as_float(a0); l1 = __int_as_float(a1);
                l2 = __int_as_float(a2); l3 = __int_as_float(a3);
                l4 = __int_as_float(a4); l5 = __int_as_float(a5);
                l6 = __int_as_float(a6); l7 = __int_as_float(a7);
                kp = a8; mlx = __int_as_float(a9);
            }
        } else if (lane == 0) {
            l0 = l1 = l2 = l3 = l4 = l5 = l6 = l7 = 0.0f;
            kp = k; mlx = 0.0f;
        }
        cons += 12;

        // ---- short renorm chain: el from shipped max, eu precomputed ----
        const int dk = kp - k;
        const int el = ((__float_as_int(mlx) >> 23) - 127) + dk;
        int s = el > eu ? el : eu;
        s = s > 0 ? s : 0;
        const int kt = k + s;                        // tile frame
        int hl = dk - s;
        hl = hl > 126 ? 126 : hl;
        const float fa = (hl < -126) ? 0.0f : __int_as_float((hl + 127) << 23);
        const float uf = (s > 126) ? 0.0f : __int_as_float((127 - s) << 23);
        l0 *= fa; l1 *= fa; l2 *= fa; l3 *= fa;
        l4 *= fa; l5 *= fa; l6 *= fa; l7 *= fa;
        float p0 = u0 * uf, p1 = u1 * uf, p2 = u2 * uf, p3 = u3 * uf;
        float p4 = u4 * uf, p5 = u5 * uf, p6 = u6 * uf, p7 = u7 * uf;
        float dl = dgW * uf;

        // ---- row costs (chain-independent address) ----
        int ridx = ts - lane;
        ridx = ridx < 0 ? 0 : (ridx > RB - 1 ? RB - 1 : ridx);
        const float4 ca = *(const float4*)&cs[ROWS * ridx];
        const float4 cb = *(const float4*)&cs[ROWS * ridx + 4];

        // ---- 64 cells: W(i,j) = (up_j + up_{j-1}) + c_i * left ----
        #define ROWSTEP(cr, lv, outv)                                       \
            {                                                               \
                const float a0_ = p0 + dl;  const float a1_ = p1 + p0;      \
                const float a2_ = p2 + p1;  const float a3_ = p3 + p2;      \
                const float a4_ = p4 + p3;  const float a5_ = p5 + p4;      \
                const float a6_ = p6 + p5;  const float a7_ = p7 + p6;      \
                const float t0_ = fmaf(cr, lv,  a0_);                       \
                const float t1_ = fmaf(cr, t0_, a1_);                       \
                const float t2_ = fmaf(cr, t1_, a2_);                       \
                const float t3_ = fmaf(cr, t2_, a3_);                       \
                const float t4_ = fmaf(cr, t3_, a4_);                       \
                const float t5_ = fmaf(cr, t4_, a5_);                       \
                const float t6_ = fmaf(cr, t5_, a6_);                       \
                const float t7_ = fmaf(cr, t6_, a7_);                       \
                outv = t7_; dl = lv;                                        \
                p0 = t0_; p1 = t1_; p2 = t2_; p3 = t3_;                     \
                p4 = t4_; p5 = t5_; p6 = t6_; p7 = t7_;                     \
            }
        ROWSTEP(ca.x, l0, nb0)
        ROWSTEP(ca.y, l1, nb1)
        ROWSTEP(ca.z, l2, nb2)
        ROWSTEP(ca.w, l3, nb3)
        ROWSTEP(cb.x, l4, nb4)
        ROWSTEP(cb.y, l5, nb5)
        ROWSTEP(cb.z, l6, nb6)
        ROWSTEP(cb.w, l7, nb7)
        #undef ROWSTEP

        // ---- tile tail: commit raw + precompute next-slot exponents ----
        u0 = p0; u1 = p1; u2 = p2; u3 = p3;
        u4 = p4; u5 = p5; u6 = p6; u7 = p7;
        dgW = dl;                                    // frame kt
        k = kt;
        const float mxu = fmaxf(fmaxf(fmaxf(p0, p1), fmaxf(p2, p3)),
                                fmaxf(fmaxf(p4, p5), fmaxf(p6, p7)));
        eu = (__float_as_int(mxu) >> 23) - 127;
        mnb = fmaxf(fmaxf(fmaxf(nb0, nb1), fmaxf(nb2, nb3)),
                    fmaxf(fmaxf(nb4, nb5), fmaxf(nb6, nb7)));

        // ---- publish (warp0 lane31): predicated plain stores ----
        asm volatile(
            "{\n\t"
            ".reg .pred p;\n\t"
            "setp.ne.s32 p, %9, 0;\n\t"
            "@p st.shared.v4.f32 [%8], {%0,%1,%2,%3};\n\t"
            "@p st.shared.v4.f32 [%8+16], {%4,%5,%6,%7};\n\t"
            "@p st.shared.b32 [%8+32], %10;\n\t"
            "@p st.shared.b32 [%8+36], %11;\n\t"
            "}"
            :: "f"(nb0),"f"(nb1),"f"(nb2),"f"(nb3),
               "f"(nb4),"f"(nb5),"f"(nb6),"f"(nb7),
               "r"(paddr), "r"(pub), "r"(k), "f"(mnb) : "memory");
        paddr += 48;
    }

    if (q == NTH - 1) {
        // R(T,T)*log2e = P - k - log2(W_raw); unscale by ln2; mean over batches.
        float Rl2 = P - (float)k - __log2f(u7);
        atomicAdd(out, Rl2 * 0.6931471805599453f * (1.0f / BATCH));
    }
}

extern "C" void kernel_launch(void* const* d_in, const int* in_sizes, int n_in,
                              void* d_out, int out_size) {
    const float* x = (const float*)d_in[0];
    const float* y = (const float*)d_in[1];
    cudaMemsetAsync(d_out, 0, sizeof(float));
    softdtw_kernel<<<BATCH, NTH>>>(x, y, (float*)d_out);
}

// round 16
// speedup vs baseline: 1.1130x; 1.1130x over previous
#include <cuda_runtime.h>

// SoftDTW-variant, gamma=1, B=32, T=512, row-broadcast cost ds[i]=(x[i]-y[i])^2.
// Linear-weight domain: W(i,j) = 2^(P(i) - R(i,j)*log2e), P(i)=sum_{r<=i} ds'[r].
//   W(i,j) = W(i-1,j) + W(i-1,j-1) + c_i * W(i,j-1),  c_i = 2^(-ds'[i]) <= 1
// Guard-free commits, raw u, joint pre-tile renorm (R13-proven numerics).
// 2 warps/batch, 8 cols/lane, 8 rows/superstep, 127 wall slots, R13 seam.
//
// R15: software-pipelined handoff — each row's boundary shfl (and lane31 STS)
// issues mid-tile right after that row completes, so next iter's l_r arrive
// during this iter's tile; kp-shfl issues right after renorm. Shfl latency
// leaves the loop-carried chain. Row-0 renorm fold saves 8 fma-pipe ops.

#define TLEN  512
#define BATCH 32
#define NTH   64
#define ROWS  8
#define RB    (TLEN / ROWS)       // 64 row-blocks
#define WSUP  (RB + 31)           // 95 supersteps per warp
#define SENT  0x7fffffff

__global__ __launch_bounds__(NTH, 1) void softdtw_kernel(const float* __restrict__ x,
                                                         const float* __restrict__ y,
                                                         float* __restrict__ out) {
    __shared__ float cs[TLEN];                       // c_i = 2^{-ds'[i]}
    __shared__ float redsum[2];
    __shared__ __align__(16) int ring[WSUP * 12];    // slot: [0..7] nb, [8] k/flag, pad

    const int q    = threadIdx.x;
    const int lane = q & 31;
    const int w    = q >> 5;
    const int b    = blockIdx.x;

    // ---- prologue: 8 costs per thread ---------------------------------------
    const float L2E = 1.4426950408889634f;
    float4 xa = ((const float4*)(x + b * TLEN))[2 * q];
    float4 xb = ((const float4*)(x + b * TLEN))[2 * q + 1];
    float4 ya = ((const float4*)(y + b * TLEN))[2 * q];
    float4 yb = ((const float4*)(y + b * TLEN))[2 * q + 1];
    float e0 = (xa.x - ya.x) * (xa.x - ya.x) * L2E;
    float e1 = (xa.y - ya.y) * (xa.y - ya.y) * L2E;
    float e2 = (xa.z - ya.z) * (xa.z - ya.z) * L2E;
    float e3 = (xa.w - ya.w) * (xa.w - ya.w) * L2E;
    float e4 = (xb.x - yb.x) * (xb.x - yb.x) * L2E;
    float e5 = (xb.y - yb.y) * (xb.y - yb.y) * L2E;
    float e6 = (xb.z - yb.z) * (xb.z - yb.z) * L2E;
    float e7 = (xb.w - yb.w) * (xb.w - yb.w) * L2E;
    cs[8*q + 0] = exp2f(-e0);  cs[8*q + 1] = exp2f(-e1);
    cs[8*q + 2] = exp2f(-e2);  cs[8*q + 3] = exp2f(-e3);
    cs[8*q + 4] = exp2f(-e4);  cs[8*q + 5] = exp2f(-e5);
    cs[8*q + 6] = exp2f(-e6);  cs[8*q + 7] = exp2f(-e7);
    float mysum = ((e0 + e1) + (e2 + e3)) + ((e4 + e5) + (e6 + e7));
    #pragma unroll
    for (int o = 16; o; o >>= 1) mysum += __shfl_xor_sync(0xffffffffu, mysum, o);
    if (lane == 0) redsum[w] = mysum;
    for (int i = q; i < WSUP; i += NTH) ring[i * 12 + 8] = SENT;
    __syncthreads();
    const float P = redsum[0] + redsum[1];

    const unsigned ringsa = (unsigned)__cvta_generic_to_shared(ring);
    unsigned paddr = ringsa;                         // producer: slot ts
    unsigned caddr = ringsa + 31u * 48u;             // consumer: slot ts+31
    const int pub = (w == 0) && (lane == 31);
    const int seam_base = (w == 1);

    // ---- state --------------------------------------------------------------
    float u0=0.f,u1=0.f,u2=0.f,u3=0.f,u4=0.f,u5=0.f,u6=0.f,u7=0.f; // RAW, frame k
    float dg = (q == 0) ? 1.0f : 0.0f;               // diag input, frame k
    int   k = 0, eu = -127;
    // "received" handoff values for the CURRENT iter (pipelined from prev iter)
    float l0=0.f,l1=0.f,l2=0.f,l3=0.f,l4=0.f,l5=0.f,l6=0.f,l7=0.f;
    int   kp = 0;

    for (int ts = 0; ts < WSUP; ++ts) {
        // ---- seam: lane0 of warp1 overrides its l/kp from the ring ----
        float rv0=0.f,rv1=0.f,rv2=0.f,rv3=0.f,rv4=0.f,rv5=0.f,rv6=0.f,rv7=0.f;
        int kv = k;
        const int seam = seam_base & (ts < RB);
        asm volatile(
            "{\n\t"
            ".reg .pred p;\n\t"
            "setp.eq.s32 p, %10, 0;\n\t"
            "@p bra SKIP_%=;\n\t"
            "POLL_%=:\n\t"
            "ld.acquire.cta.shared.b32 %8, [%9+32];\n\t"
            "setp.eq.s32 p, %8, 2147483647;\n\t"
            "@p bra POLL_%=;\n\t"
            "ld.shared.v4.f32 {%0,%1,%2,%3}, [%9];\n\t"
            "ld.shared.v4.f32 {%4,%5,%6,%7}, [%9+16];\n\t"
            "SKIP_%=:\n\t"
            "}"
            : "+f"(rv0),"+f"(rv1),"+f"(rv2),"+f"(rv3),
              "+f"(rv4),"+f"(rv5),"+f"(rv6),"+f"(rv7),"+r"(kv)
            : "r"(caddr), "r"(seam) : "memory");
        caddr += 48;

        const bool z = (lane == 0);                  // rv/kv preset so this is
        l0 = z ? rv0 : l0;  l1 = z ? rv1 : l1;       // 0/k when no seam: exactly
        l2 = z ? rv2 : l2;  l3 = z ? rv3 : l3;       // the column-0 boundary.
        l4 = z ? rv4 : l4;  l5 = z ? rv5 : l5;
        l6 = z ? rv6 : l6;  l7 = z ? rv7 : l7;
        kp = z ? kv  : kp;

        // ---- joint pre-tile renorm (alu-heavy; fma gaps absorb it) ----
        const int dk = kp - k;
        const float mlx = fmaxf(fmaxf(fmaxf(l0, l1), fmaxf(l2, l3)),
                                fmaxf(fmaxf(l4, l5), fmaxf(l6, l7)));
        const int el = ((__float_as_int(mlx) >> 23) - 127) + dk;
        int s = el > eu ? el : eu;
        s = s > 0 ? s : 0;
        const int kt = k + s;                        // tile frame
        int hl = dk - s;
        hl = hl > 126 ? 126 : hl;
        const float fa = (hl < -126) ? 0.0f : __int_as_float((hl + 127) << 23);
        const float uf = (s > 126) ? 0.0f : __int_as_float((127 - s) << 23);
        l0 *= fa; l1 *= fa; l2 *= fa; l3 *= fa;
        l4 *= fa; l5 *= fa; l6 *= fa; l7 *= fa;

        // kp for NEXT iter: issue now (latency hidden under the tile)
        const int kpn = __shfl_up_sync(0xffffffffu, kt, 1);

        // ---- row costs (chain-independent) ----
        int ridx = ts - lane;
        ridx = ridx < 0 ? 0 : (ridx > RB - 1 ? RB - 1 : ridx);
        const float4 ca = *(const float4*)&cs[ROWS * ridx];
        const float4 cb = *(const float4*)&cs[ROWS * ridx + 4];

        // ---- row 0 (uf folded): t_j = c0*t_{j-1} + (u_j + u_{j-1})*uf ----
        float p0, p1, p2, p3, p4, p5, p6, p7, dl;
        float ln0, ln1, ln2, ln3, ln4, ln5, ln6, ln7;   // next iter's l (pipelined)
        {
            const float v0 = (u0 + dg) * uf;  const float v1 = (u1 + u0) * uf;
            const float v2 = (u2 + u1) * uf;  const float v3 = (u3 + u2) * uf;
            const float v4 = (u4 + u3) * uf;  const float v5 = (u5 + u4) * uf;
            const float v6 = (u6 + u5) * uf;  const float v7 = (u7 + u6) * uf;
            p0 = fmaf(ca.x, l0, v0);
            p1 = fmaf(ca.x, p0, v1);
            p2 = fmaf(ca.x, p1, v2);
            p3 = fmaf(ca.x, p2, v3);
            p4 = fmaf(ca.x, p3, v4);
            p5 = fmaf(ca.x, p4, v5);
            p6 = fmaf(ca.x, p5, v6);
            p7 = fmaf(ca.x, p6, v7);
            dl = l0;
        }
        ln0 = __shfl_up_sync(0xffffffffu, p7, 1);
        asm volatile("{ .reg .pred p; setp.ne.s32 p, %2, 0;"
                     " @p st.shared.b32 [%0], %1; }"
                     :: "r"(paddr), "f"(p7), "r"(pub) : "memory");

        // ---- rows 1..7: W = (up_j + up_{j-1}) + c_r * left; shfl per row ----
        #define ROWSTEP(cr, lv, lnv, off)                                    \
            {                                                                \
                const float a0_ = p0 + dl;  const float a1_ = p1 + p0;       \
                const float a2_ = p2 + p1;  const float a3_ = p3 + p2;       \
                const float a4_ = p4 + p3;  const float a5_ = p5 + p4;       \
                const float a6_ = p6 + p5;  const float a7_ = p7 + p6;       \
                p0 = fmaf(cr, lv, a0_);                                      \
                p1 = fmaf(cr, p0, a1_);                                      \
                p2 = fmaf(cr, p1, a2_);                                      \
                p3 = fmaf(cr, p2, a3_);                                      \
                p4 = fmaf(cr, p3, a4_);                                      \
                p5 = fmaf(cr, p4, a5_);                                      \
                p6 = fmaf(cr, p5, a6_);                                      \
                p7 = fmaf(cr, p6, a7_);                                      \
                dl = lv;                                                     \
                lnv = __shfl_up_sync(0xffffffffu, p7, 1);                    \
                asm volatile("{ .reg .pred p; setp.ne.s32 p, %2, 0;"         \
                             " @p st.shared.b32 [%0+" #off "], %1; }"        \
                             :: "r"(paddr), "f"(p7), "r"(pub) : "memory");   \
            }
        ROWSTEP(ca.y, l1, ln1, 4)
        ROWSTEP(ca.z, l2, ln2, 8)
        ROWSTEP(ca.w, l3, ln3, 12)
        ROWSTEP(cb.x, l4, ln4, 16)
        ROWSTEP(cb.y, l5, ln5, 20)
        ROWSTEP(cb.z, l6, ln6, 24)
        ROWSTEP(cb.w, l7, ln7, 28)
        #undef ROWSTEP

        // ---- tail: commit raw, eu for next renorm (alu), release flag ----
        u0 = p0; u1 = p1; u2 = p2; u3 = p3;
        u4 = p4; u5 = p5; u6 = p6; u7 = p7;
        dg = l7;                                     // scaled, frame kt
        k = kt;
        const float mxu = fmaxf(fmaxf(fmaxf(p0, p1), fmaxf(p2, p3)),
                                fmaxf(fmaxf(p4, p5), fmaxf(p6, p7)));
        eu = (__float_as_int(mxu) >> 23) - 127;
        asm volatile("{ .reg .pred p; setp.ne.s32 p, %2, 0;"
                     " @p st.release.cta.shared.b32 [%0+32], %1; }"
                     :: "r"(paddr), "r"(kt), "r"(pub) : "memory");
        paddr += 48;

        // rename pipelined handoff values for the next iteration
        l0 = ln0; l1 = ln1; l2 = ln2; l3 = ln3;
        l4 = ln4; l5 = ln5; l6 = ln6; l7 = ln7;
        kp = kpn;
    }

    if (q == NTH - 1) {
        // R(T,T)*log2e = P - k - log2(W_raw); unscale by ln2; mean over batches.
        float Rl2 = P - (float)k - __log2f(u7);
        atomicAdd(out, Rl2 * 0.6931471805599453f * (1.0f / BATCH));
    }
}

extern "C" void kernel_launch(void* const* d_in, const int* in_sizes, int n_in,
                              void* d_out, int out_size) {
    const float* x = (const float*)d_in[0];
    const float* y = (const float*)d_in[1];
    cudaMemsetAsync(d_out, 0, sizeof(float));
    softdtw_kernel<<<BATCH, NTH>>>(x, y, (float*)d_out);
}